// round 1
// baseline (speedup 1.0000x reference)
#include <cuda_runtime.h>

// ---------------------------------------------------------------------------
// ECGSegMCULBit: quantized 1-D CNN pipeline.
// Numerics: lbit = round-half-even(x*64)/64 (exact scaling). Conv/pool/softmax
// sums are exact in fp32 (all operands are multiples of 1/64 or 1/4096, small
// magnitude). tanh uses the XLA/Eigen rational polynomial so quantization
// boundaries match the JAX reference. All true divisions use __fdiv_rn; the
// softmax polynomial and upsample lerp use non-contracted rn intrinsics to
// mirror XLA's non-fused mul/add HLO.
// ---------------------------------------------------------------------------

#define DEVFN __device__ __forceinline__

static const unsigned BUFN = 128u * 64u * 5016u; // largest intermediate
__device__ float g_buf0[128u * 64u * 5016u];
__device__ float g_buf1[128u * 64u * 5016u];

DEVFN float lbitf(float x) { return rintf(__fmul_rn(x, 64.0f)) * 0.015625f; }

// XLA / Eigen float tanh approximation (matches jnp.tanh lowering).
DEVFN float tanh_xla(float x) {
    const float kClamp = 7.99881172180175781f;
    float ax = fabsf(x);
    float xc = fminf(fmaxf(x, -kClamp), kClamp);
    float x2 = __fmul_rn(xc, xc);
    float p = -2.76076847742355e-16f;
    p = __fmaf_rn(x2, p, 2.00018790482477e-13f);
    p = __fmaf_rn(x2, p, -8.60467152213735e-11f);
    p = __fmaf_rn(x2, p, 5.12229709037114e-08f);
    p = __fmaf_rn(x2, p, 1.48572235717979e-05f);
    p = __fmaf_rn(x2, p, 6.37261928875436e-04f);
    p = __fmaf_rn(x2, p, 4.89352455891786e-03f);
    p = __fmul_rn(xc, p);
    float q = 1.19825839466702e-06f;
    q = __fmaf_rn(x2, q, 1.18534705686654e-04f);
    q = __fmaf_rn(x2, q, 2.26843463243900e-03f);
    q = __fmaf_rn(x2, q, 4.89352518554385e-03f);
    float r = __fdiv_rn(p, q);
    return (ax < 0.0004f) ? x : r;
}

DEVFN float lbit_tanh(float x) { return lbitf(tanh_xla(x)); }

// ---------------------------------------------------------------------------
// Stage 1: pad (236,100) + /8 + lbit + avgpool(4,4) + lbit.
// in x:[128,12,5000] -> out:[128,12,1334]
// ---------------------------------------------------------------------------
__global__ void k_pad_pool4(const float* __restrict__ x, float* __restrict__ out) {
    const int C = 12, Lout = 1334, Lin = 5000;
    int idx = blockIdx.x * blockDim.x + threadIdx.x;
    int total = 128 * C * Lout;
    if (idx >= total) return;
    int j = idx % Lout;
    int bc = idx / Lout;
    float s = 0.0f;
#pragma unroll
    for (int u = 0; u < 4; u++) {
        int srcp = 4 * j + u - 236;
        float v = 0.0f;
        if (srcp >= 0 && srcp < Lin)
            v = lbitf(__fmul_rn(x[(size_t)bc * Lin + srcp], 0.125f));
        s = __fadd_rn(s, v);
    }
    out[idx] = lbitf(__fmul_rn(s, 0.25f));
}

// ---------------------------------------------------------------------------
// Generic qconv: lbit_tanh(input), weight = binarize or lbit_tanh, conv VALID,
// lbit(output). Layout [B][C][L]. One block = (batch, 128-pos tile).
// ---------------------------------------------------------------------------
template <int I, int O, int K, bool BIN>
__global__ void k_qconv(const float* __restrict__ in, const float* __restrict__ w,
                        float* __restrict__ out, int Lin) {
    const int TP = 128;
    const int XT = TP + K - 1;
    int Lout = Lin - K + 1;
    int b = blockIdx.y;
    int tile0 = blockIdx.x * TP;

    __shared__ float sw[O * I * K];
    __shared__ float sx[I * XT];

    for (int t = threadIdx.x; t < O * I * K; t += TP) {
        float v = w[t];
        sw[t] = BIN ? (v >= 0.0f ? 1.0f : -1.0f) : lbit_tanh(v);
    }
    for (int t = threadIdx.x; t < I * XT; t += TP) {
        int i = t / XT;
        int p = t % XT;
        int gp = tile0 + p;
        sx[t] = (gp < Lin) ? lbit_tanh(in[((size_t)b * I + i) * Lin + gp]) : 0.0f;
    }
    __syncthreads();

    int pos = tile0 + threadIdx.x;
    if (pos >= Lout) return;

    for (int o = 0; o < O; o++) {
        float acc = 0.0f;
#pragma unroll
        for (int i = 0; i < I; i++)
#pragma unroll
            for (int k = 0; k < K; k++)
                acc = __fmaf_rn(sw[(o * I + i) * K + k], sx[i * XT + threadIdx.x + k], acc);
        out[((size_t)b * O + o) * Lout + pos] = lbitf(acc);
    }
}

// ---------------------------------------------------------------------------
// avgpool: lbit(in), window-sum (exact), /k (rn div), lbit.
// ---------------------------------------------------------------------------
__global__ void k_avgpool(const float* __restrict__ in, float* __restrict__ out,
                          int C, int Lin, int Lout, int k, int s) {
    int idx = blockIdx.x * blockDim.x + threadIdx.x;
    int total = 128 * C * Lout;
    if (idx >= total) return;
    int j = idx % Lout;
    int bc = idx / Lout;
    const float* p = in + (size_t)bc * Lin + (size_t)j * s;
    float sum = 0.0f;
    for (int u = 0; u < k; u++) sum = __fadd_rn(sum, lbitf(p[u]));
    out[idx] = lbitf(__fdiv_rn(sum, (float)k));
}

// ---------------------------------------------------------------------------
// poly_softmax over 64 channels. One thread per (batch, position); channel
// loop fully unrolled so v[] stays in registers. Reads/writes coalesced in pos.
// ---------------------------------------------------------------------------
__global__ void k_softmax64(const float* __restrict__ in, float* __restrict__ out, int L) {
    int idx = blockIdx.x * blockDim.x + threadIdx.x;
    if (idx >= 128 * L) return;
    int b = idx / L;
    int pos = idx % L;
    const float* ip = in + (size_t)b * 64 * L + pos;

    float v[64];
    float vmax = -3.0e38f;
#pragma unroll
    for (int c = 0; c < 64; c++) {
        v[c] = lbitf(ip[(size_t)c * L]);
        vmax = fmaxf(vmax, v[c]);
    }
    float sum = 0.0f;
#pragma unroll
    for (int c = 0; c < 64; c++) {
        float d  = __fsub_rn(vmax, v[c]);
        float d2 = __fmul_rn(__fmul_rn(d, d), 0.5f);           // d*d/2
        float d3 = __fdiv_rn(__fmul_rn(d2, d), 3.0f);          // d2*d/3
        float d4 = __fmul_rn(__fmul_rn(d3, d), 0.25f);         // d3*d/4
        float den = __fadd_rn(__fadd_rn(__fadd_rn(__fadd_rn(1.0f, d), d2), d3), d4);
        float o = lbitf(__fdiv_rn(1.0f, den));
        v[c] = o;
        sum = __fadd_rn(sum, o);                               // exact (multiples of 1/64)
    }
    float* op = out + (size_t)b * 64 * L + pos;
#pragma unroll
    for (int c = 0; c < 64; c++) op[(size_t)c * L] = lbitf(__fdiv_rn(v[c], sum));
}

// ---------------------------------------------------------------------------
// Linear upsample (align_corners=False) + crop [scale/2 : n*scale - (scale - scale/2)].
// out length = n*scale - scale. C = 64.
// ---------------------------------------------------------------------------
__global__ void k_upsample(const float* __restrict__ in, float* __restrict__ out,
                           int n, int scale, int Lout) {
    int idx = blockIdx.x * blockDim.x + threadIdx.x;
    int total = 128 * 64 * Lout;
    if (idx >= total) return;
    int j = idx % Lout;
    int bc = idx / Lout;
    int i = j + scale / 2;
    float fi  = __fadd_rn((float)i, 0.5f);
    float src = fmaxf(__fsub_rn(__fdiv_rn(fi, (float)scale), 0.5f), 0.0f);
    int i0 = (int)floorf(src);
    int i1 = min(i0 + 1, n - 1);
    float w = __fsub_rn(src, (float)i0);
    const float* p = in + (size_t)bc * n;
    float x0 = lbitf(p[i0]);
    float x1 = lbitf(p[i1]);
    float val = __fadd_rn(__fmul_rn(x0, __fsub_rn(1.0f, w)), __fmul_rn(x1, w));
    out[idx] = lbitf(val);
}

// ---------------------------------------------------------------------------
// Final: qconv uw5 (8 -> 4, k=1, non-binary) fused with crop[16:] + transpose
// to [B, 5000, 4]. float4 stores.
// ---------------------------------------------------------------------------
__global__ void k_final(const float* __restrict__ in, const float* __restrict__ w,
                        float* __restrict__ out, int Lin, int off) {
    __shared__ float sw[32]; // 4*8
    if (threadIdx.x < 32) sw[threadIdx.x] = lbit_tanh(w[threadIdx.x]);
    __syncthreads();
    int idx = blockIdx.x * blockDim.x + threadIdx.x;
    if (idx >= 128 * 5000) return;
    int b = idx / 5000;
    int t = idx % 5000;
    float xi[8];
#pragma unroll
    for (int i = 0; i < 8; i++)
        xi[i] = lbit_tanh(in[((size_t)b * 8 + i) * Lin + t + off]);
    float rr[4];
#pragma unroll
    for (int o = 0; o < 4; o++) {
        float acc = 0.0f;
#pragma unroll
        for (int i = 0; i < 8; i++) acc = __fmaf_rn(sw[o * 8 + i], xi[i], acc);
        rr[o] = lbitf(acc);
    }
    float4* o4 = (float4*)(out + (size_t)idx * 4);
    *o4 = make_float4(rr[0], rr[1], rr[2], rr[3]);
}

// ---------------------------------------------------------------------------
// Host launcher. Ping-pong g_buf0/g_buf1. Inputs (metadata order):
// x, dw1..dw9, uw1..uw5. Output float32 [128,5000,4].
// ---------------------------------------------------------------------------
extern "C" void kernel_launch(void* const* d_in, const int* in_sizes, int n_in,
                              void* d_out, int out_size) {
    (void)in_sizes; (void)n_in; (void)out_size;
    float *b0, *b1;
    cudaGetSymbolAddress((void**)&b0, g_buf0);
    cudaGetSymbolAddress((void**)&b1, g_buf1);

    const float* x = (const float*)d_in[0];
    const float* W[15];
    for (int i = 1; i < 15; i++) W[i] = (const float*)d_in[i];
    float* out = (float*)d_out;

    auto cg = [](int Lout) { return dim3((unsigned)((Lout + 127) / 128), 128); };

    // ---- down path ----
    { int total = 128 * 12 * 1334; k_pad_pool4<<<(total + 255) / 256, 256>>>(x, b0); }
    k_qconv<12, 4, 1, false><<<cg(1334), 128>>>(b0, W[1], b1, 1334);
    k_qconv<4, 4, 3, false><<<cg(1332), 128>>>(b1, W[2], b0, 1334);
    k_qconv<4, 64, 3, true><<<cg(1330), 128>>>(b0, W[3], b1, 1332);
    { int total = 128 * 64 * 266; k_avgpool<<<(total + 255) / 256, 256>>>(b1, b0, 64, 1330, 266, 5, 5); }
    k_softmax64<<<(128 * 266 + 127) / 128, 128>>>(b0, b1, 266);
    k_qconv<64, 4, 1, true><<<cg(266), 128>>>(b1, W[4], b0, 266);
    k_qconv<4, 4, 3, false><<<cg(264), 128>>>(b0, W[5], b1, 266);
    k_qconv<4, 64, 3, true><<<cg(262), 128>>>(b1, W[6], b0, 264);
    { int total = 128 * 64 * 260; k_avgpool<<<(total + 255) / 256, 256>>>(b0, b1, 64, 262, 260, 3, 1); }
    k_softmax64<<<(128 * 260 + 127) / 128, 128>>>(b1, b0, 260);
    k_qconv<64, 4, 1, true><<<cg(260), 128>>>(b0, W[7], b1, 260);
    k_qconv<4, 4, 3, false><<<cg(258), 128>>>(b1, W[8], b0, 260);
    k_qconv<4, 64, 3, true><<<cg(256), 128>>>(b0, W[9], b1, 258);
    { int total = 128 * 64 * 252; k_avgpool<<<(total + 255) / 256, 256>>>(b1, b0, 64, 256, 252, 5, 1); }
    k_softmax64<<<(128 * 252 + 127) / 128, 128>>>(b0, b1, 252);

    // ---- up path ----
    { int total = 128 * 64 * 1255; k_upsample<<<(total + 255) / 256, 256>>>(b1, b0, 252, 5, 1255); }
    k_qconv<64, 8, 1, true><<<cg(1255), 128>>>(b0, W[10], b1, 1255);
    k_qconv<8, 8, 1, false><<<cg(1255), 128>>>(b1, W[11], b0, 1255);
    k_qconv<8, 64, 1, true><<<cg(1255), 128>>>(b0, W[12], b1, 1255);
    k_softmax64<<<(128 * 1255 + 127) / 128, 128>>>(b1, b0, 1255);
    { int total = 128 * 64 * 5016; k_upsample<<<(total + 255) / 256, 256>>>(b0, b1, 1255, 4, 5016); }
    k_qconv<64, 8, 1, true><<<cg(5016), 128>>>(b1, W[13], b0, 5016);
    k_final<<<(128 * 5000 + 255) / 256, 256>>>(b0, W[14], out, 5016, 16);
}

// round 2
// speedup vs baseline: 1.6276x; 1.6276x over previous
#include <cuda_runtime.h>

// ---------------------------------------------------------------------------
// ECGSegMCULBit fused pipeline (6 kernels).
// Numerics identical to the round-1 bit-exact version: lbit = rint(x*64)/64,
// XLA/Eigen tanh polynomial, __fdiv_rn divisions, rn mul/add (no contraction),
// identical accumulation orders. Only spatial scheduling changed.
// ---------------------------------------------------------------------------

#define DEVFN __device__ __forceinline__

__device__ float g_buf0[128u * 64u * 1255u];
__device__ float g_buf1[128u * 64u * 1255u];

DEVFN float lbitf(float x) { return rintf(__fmul_rn(x, 64.0f)) * 0.015625f; }

DEVFN float tanh_xla(float x) {
    const float kClamp = 7.99881172180175781f;
    float ax = fabsf(x);
    float xc = fminf(fmaxf(x, -kClamp), kClamp);
    float x2 = __fmul_rn(xc, xc);
    float p = -2.76076847742355e-16f;
    p = __fmaf_rn(x2, p, 2.00018790482477e-13f);
    p = __fmaf_rn(x2, p, -8.60467152213735e-11f);
    p = __fmaf_rn(x2, p, 5.12229709037114e-08f);
    p = __fmaf_rn(x2, p, 1.48572235717979e-05f);
    p = __fmaf_rn(x2, p, 6.37261928875436e-04f);
    p = __fmaf_rn(x2, p, 4.89352455891786e-03f);
    p = __fmul_rn(xc, p);
    float q = 1.19825839466702e-06f;
    q = __fmaf_rn(x2, q, 1.18534705686654e-04f);
    q = __fmaf_rn(x2, q, 2.26843463243900e-03f);
    q = __fmaf_rn(x2, q, 4.89352518554385e-03f);
    float r = __fdiv_rn(p, q);
    return (ax < 0.0004f) ? x : r;
}

DEVFN float lbit_tanh(float x) { return lbitf(tanh_xla(x)); }

// softmax poly for one value (d = vmax - v), returns lbit(1/den)
DEVFN float smax_poly(float vmax, float v) {
    float d  = __fsub_rn(vmax, v);
    float d2 = __fmul_rn(__fmul_rn(d, d), 0.5f);
    float d3 = __fdiv_rn(__fmul_rn(d2, d), 3.0f);
    float d4 = __fmul_rn(__fmul_rn(d3, d), 0.25f);
    float den = __fadd_rn(__fadd_rn(__fadd_rn(__fadd_rn(1.0f, d), d2), d3), d4);
    return lbitf(__fdiv_rn(1.0f, den));
}

// ---------------------------------------------------------------------------
// K1: pad(236,100) + /8 + lbit + avgpool(4,4) + lbit + qconv(12->4,k1,nonbin)
// x:[128,12,5000] -> out:[128,4,1334]
// ---------------------------------------------------------------------------
__global__ void k_head(const float* __restrict__ x, const float* __restrict__ w1,
                       float* __restrict__ out) {
    const int Lout = 1334, Lin = 5000;
    __shared__ float sw[48];
    if (threadIdx.x < 48) sw[threadIdx.x] = lbit_tanh(w1[threadIdx.x]);
    __syncthreads();
    int idx = blockIdx.x * blockDim.x + threadIdx.x;
    if (idx >= 128 * Lout) return;
    int pos = idx % Lout;
    int b = idx / Lout;
    float t[12];
#pragma unroll
    for (int c = 0; c < 12; c++) {
        const float* xp = x + ((size_t)b * 12 + c) * Lin;
        float s = 0.0f;
#pragma unroll
        for (int u = 0; u < 4; u++) {
            int sp = 4 * pos + u - 236;
            float v = 0.0f;
            if (sp >= 0 && sp < Lin) v = lbitf(__fmul_rn(xp[sp], 0.125f));
            s = __fadd_rn(s, v);
        }
        t[c] = lbit_tanh(lbitf(__fmul_rn(s, 0.25f)));
    }
#pragma unroll
    for (int o = 0; o < 4; o++) {
        float acc = 0.0f;
#pragma unroll
        for (int c = 0; c < 12; c++) acc = __fmaf_rn(sw[o * 12 + c], t[c], acc);
        out[((size_t)b * 4 + o) * Lout + pos] = lbitf(acc);
    }
}

// ---------------------------------------------------------------------------
// K2/K3/K4: qconv(4->4,k3,nonbin) + qconv(4->64,k3,bin) + avgpool(PW,PS)
//           + poly_softmax [+ qconv(64->4,k1,bin) if TAIL]
// ---------------------------------------------------------------------------
template <int PW, int PS, int TP, bool TAIL>
__global__ __launch_bounds__(TP)
void k_mid(const float* __restrict__ in, int Lin, int Lout,
           const float* __restrict__ w2, const float* __restrict__ w3,
           const float* __restrict__ wt, float* __restrict__ out) {
    const int NT2 = PS * (TP - 1) + PW + 2;   // conv2-out (tanh'd) positions needed
    const int NA  = PS * (TP - 1) + PW + 4;   // conv2-in positions needed
    __shared__ float sxa[4 * NA];
    __shared__ float st2[4 * NT2];
    __shared__ float sw2[48];
    __shared__ float sw3[64 * 4 * 3];
    __shared__ float swt[256];

    int b = blockIdx.y;
    int j0 = blockIdx.x * TP;
    int base = PS * j0;
    int tid = threadIdx.x;

    for (int t = tid; t < 48; t += TP) sw2[t] = lbit_tanh(w2[t]);
    for (int t = tid; t < 64 * 4 * 3; t += TP) sw3[t] = (w3[t] >= 0.0f) ? 1.0f : -1.0f;
    if (TAIL)
        for (int t = tid; t < 256; t += TP) swt[t] = (wt[t] >= 0.0f) ? 1.0f : -1.0f;

    for (int t = tid; t < 4 * NA; t += TP) {
        int i = t / NA, p = t % NA;
        int g = base + p;
        sxa[t] = (g < Lin) ? lbit_tanh(in[((size_t)b * 4 + i) * Lin + g]) : 0.0f;
    }
    __syncthreads();

    // conv2 (4->4, k3) + lbit + tanh into st2
    for (int q = tid; q < NT2; q += TP) {
#pragma unroll
        for (int o = 0; o < 4; o++) {
            float acc = 0.0f;
#pragma unroll
            for (int i = 0; i < 4; i++)
#pragma unroll
                for (int k = 0; k < 3; k++)
                    acc = __fmaf_rn(sw2[(o * 4 + i) * 3 + k], sxa[i * NA + q + k], acc);
            st2[o * NT2 + q] = lbit_tanh(lbitf(acc));
        }
    }
    __syncthreads();

    int j = j0 + tid;
    if (j >= Lout) return;

    // per-thread register window of conv3 input
    float xr[4][PW + 2];
#pragma unroll
    for (int i = 0; i < 4; i++)
#pragma unroll
        for (int w = 0; w < PW + 2; w++) xr[i][w] = st2[i * NT2 + PS * tid + w];

    // conv3 (4->64,k3,bin) + lbit + avgpool + lbit -> v[64]
    float v[64];
    float vmax = -3.0e38f;
#pragma unroll
    for (int c = 0; c < 64; c++) {
        float psum = 0.0f;
#pragma unroll
        for (int u = 0; u < PW; u++) {
            float acc = 0.0f;
#pragma unroll
            for (int i = 0; i < 4; i++)
#pragma unroll
                for (int k = 0; k < 3; k++)
                    acc = __fmaf_rn(sw3[(c * 4 + i) * 3 + k], xr[i][u + k], acc);
            psum = __fadd_rn(psum, lbitf(acc));
        }
        v[c] = lbitf(__fdiv_rn(psum, (float)PW));
        vmax = fmaxf(vmax, v[c]);
    }
    // softmax
    float sum = 0.0f;
#pragma unroll
    for (int c = 0; c < 64; c++) {
        float o = smax_poly(vmax, v[c]);
        v[c] = o;
        sum = __fadd_rn(sum, o);
    }
    if (TAIL) {
        float acc0 = 0.0f, acc1 = 0.0f, acc2 = 0.0f, acc3 = 0.0f;
#pragma unroll
        for (int c = 0; c < 64; c++) {
            float tv = lbit_tanh(lbitf(__fdiv_rn(v[c], sum)));
            acc0 = __fmaf_rn(swt[0 * 64 + c], tv, acc0);
            acc1 = __fmaf_rn(swt[1 * 64 + c], tv, acc1);
            acc2 = __fmaf_rn(swt[2 * 64 + c], tv, acc2);
            acc3 = __fmaf_rn(swt[3 * 64 + c], tv, acc3);
        }
        out[((size_t)b * 4 + 0) * Lout + j] = lbitf(acc0);
        out[((size_t)b * 4 + 1) * Lout + j] = lbitf(acc1);
        out[((size_t)b * 4 + 2) * Lout + j] = lbitf(acc2);
        out[((size_t)b * 4 + 3) * Lout + j] = lbitf(acc3);
    } else {
#pragma unroll
        for (int c = 0; c < 64; c++)
            out[((size_t)b * 64 + c) * Lout + j] = lbitf(__fdiv_rn(v[c], sum));
    }
}

// ---------------------------------------------------------------------------
// K5: upsample(x5) + qconv(64->8,bin) + qconv(8->8,nonbin) + qconv(8->64,bin)
//     + poly_softmax.  in:[128,64,252] -> out:[128,64,1255]
// ---------------------------------------------------------------------------
__global__ __launch_bounds__(128)
void k_up5(const float* __restrict__ in, const float* __restrict__ w1,
           const float* __restrict__ w2, const float* __restrict__ w3,
           float* __restrict__ out) {
    const int n = 252, Lout = 1255;
    __shared__ float sb1[512];  // 8x64 bin
    __shared__ float sw2[64];   // 8x8 tanh
    __shared__ float sb3[512];  // 64x8 bin
    for (int t = threadIdx.x; t < 512; t += 128) sb1[t] = (w1[t] >= 0.0f) ? 1.0f : -1.0f;
    for (int t = threadIdx.x; t < 64; t += 128) sw2[t] = lbit_tanh(w2[t]);
    for (int t = threadIdx.x; t < 512; t += 128) sb3[t] = (w3[t] >= 0.0f) ? 1.0f : -1.0f;
    __syncthreads();

    int idx = blockIdx.x * blockDim.x + threadIdx.x;
    if (idx >= 128 * Lout) return;
    int pos = idx % Lout;
    int b = idx / Lout;

    int i = pos + 2;
    float fi = __fadd_rn((float)i, 0.5f);
    float src = fmaxf(__fsub_rn(__fdiv_rn(fi, 5.0f), 0.5f), 0.0f);
    int i0 = (int)floorf(src);
    int i1 = min(i0 + 1, n - 1);
    float w = __fsub_rn(src, (float)i0);
    float w0 = __fsub_rn(1.0f, w);

    float h1[8];
#pragma unroll
    for (int o = 0; o < 8; o++) h1[o] = 0.0f;

    const float* ip = in + (size_t)b * 64 * n;
    for (int c = 0; c < 64; c++) {
        float x0 = lbitf(ip[(size_t)c * n + i0]);
        float x1 = lbitf(ip[(size_t)c * n + i1]);
        float val = lbitf(__fadd_rn(__fmul_rn(x0, w0), __fmul_rn(x1, w)));
        float t = lbit_tanh(val);
#pragma unroll
        for (int o = 0; o < 8; o++) h1[o] = __fmaf_rn(sb1[o * 64 + c], t, h1[o]);
    }
    float t1[8];
#pragma unroll
    for (int o = 0; o < 8; o++) t1[o] = lbit_tanh(lbitf(h1[o]));
    float t2[8];
#pragma unroll
    for (int o = 0; o < 8; o++) {
        float acc = 0.0f;
#pragma unroll
        for (int k = 0; k < 8; k++) acc = __fmaf_rn(sw2[o * 8 + k], t1[k], acc);
        t2[o] = lbit_tanh(lbitf(acc));
    }
    float v[64];
    float vmax = -3.0e38f;
#pragma unroll
    for (int c = 0; c < 64; c++) {
        float acc = 0.0f;
#pragma unroll
        for (int k = 0; k < 8; k++) acc = __fmaf_rn(sb3[c * 8 + k], t2[k], acc);
        v[c] = lbitf(acc);
        vmax = fmaxf(vmax, v[c]);
    }
    float sum = 0.0f;
#pragma unroll
    for (int c = 0; c < 64; c++) {
        float o = smax_poly(vmax, v[c]);
        v[c] = o;
        sum = __fadd_rn(sum, o);
    }
    float* op = out + (size_t)b * 64 * Lout + pos;
#pragma unroll
    for (int c = 0; c < 64; c++) op[(size_t)c * Lout] = lbitf(__fdiv_rn(v[c], sum));
}

// ---------------------------------------------------------------------------
// K6: upsample(x4) + qconv(64->8,bin) + qconv(8->4,nonbin) + crop[16:] +
//     transpose -> out [128,5000,4]
// ---------------------------------------------------------------------------
__global__ __launch_bounds__(128)
void k_up4(const float* __restrict__ in, const float* __restrict__ w4,
           const float* __restrict__ w5, float* __restrict__ out) {
    const int n = 1255;
    __shared__ float sb4[512];  // 8x64 bin
    __shared__ float sw5[32];   // 4x8 tanh
    for (int t = threadIdx.x; t < 512; t += 128) sb4[t] = (w4[t] >= 0.0f) ? 1.0f : -1.0f;
    if (threadIdx.x < 32) sw5[threadIdx.x] = lbit_tanh(w5[threadIdx.x]);
    __syncthreads();

    int idx = blockIdx.x * blockDim.x + threadIdx.x;
    if (idx >= 128 * 5000) return;
    int t = idx % 5000;
    int b = idx / 5000;

    int i = t + 18;  // crop 16 + internal crop l=2
    float fi = __fadd_rn((float)i, 0.5f);
    float src = fmaxf(__fsub_rn(__fdiv_rn(fi, 4.0f), 0.5f), 0.0f);
    int i0 = (int)floorf(src);
    int i1 = min(i0 + 1, n - 1);
    float w = __fsub_rn(src, (float)i0);
    float w0 = __fsub_rn(1.0f, w);

    float h[8];
#pragma unroll
    for (int o = 0; o < 8; o++) h[o] = 0.0f;

    const float* ip = in + (size_t)b * 64 * n;
    for (int c = 0; c < 64; c++) {
        float x0 = lbitf(ip[(size_t)c * n + i0]);
        float x1 = lbitf(ip[(size_t)c * n + i1]);
        float val = lbitf(__fadd_rn(__fmul_rn(x0, w0), __fmul_rn(x1, w)));
        float tv = lbit_tanh(val);
#pragma unroll
        for (int o = 0; o < 8; o++) h[o] = __fmaf_rn(sb4[o * 64 + c], tv, h[o]);
    }
    float t4[8];
#pragma unroll
    for (int o = 0; o < 8; o++) t4[o] = lbit_tanh(lbitf(h[o]));
    float rr[4];
#pragma unroll
    for (int o = 0; o < 4; o++) {
        float acc = 0.0f;
#pragma unroll
        for (int k = 0; k < 8; k++) acc = __fmaf_rn(sw5[o * 8 + k], t4[k], acc);
        rr[o] = lbitf(acc);
    }
    float4* o4 = (float4*)(out + (size_t)idx * 4);
    *o4 = make_float4(rr[0], rr[1], rr[2], rr[3]);
}

// ---------------------------------------------------------------------------
// Host launcher: 6 kernels, ping-pong g_buf0/g_buf1.
// Inputs: x, dw1..dw9, uw1..uw5.  Output float32 [128,5000,4].
// ---------------------------------------------------------------------------
extern "C" void kernel_launch(void* const* d_in, const int* in_sizes, int n_in,
                              void* d_out, int out_size) {
    (void)in_sizes; (void)n_in; (void)out_size;
    float *b0, *b1;
    cudaGetSymbolAddress((void**)&b0, g_buf0);
    cudaGetSymbolAddress((void**)&b1, g_buf1);

    const float* W[15];
    for (int i = 0; i < 15; i++) W[i] = (const float*)d_in[i];
    float* out = (float*)d_out;

    // K1: x -> b0 [128,4,1334]
    { int total = 128 * 1334; k_head<<<(total + 255) / 256, 256>>>(W[0], W[1], b0); }
    // K2: b0 -> b1 [128,4,266]   (pool 5 stride 5, tail conv dw4)
    k_mid<5, 5, 128, true><<<dim3(3, 128), 128>>>(b0, 1334, 266, W[2], W[3], W[4], b1);
    // K3: b1 -> b0 [128,4,260]   (pool 3 stride 1, tail conv dw7)
    k_mid<3, 1, 128, true><<<dim3(3, 128), 128>>>(b1, 266, 260, W[5], W[6], W[7], b0);
    // K4: b0 -> b1 [128,64,252]  (pool 5 stride 1, no tail)
    k_mid<5, 1, 128, false><<<dim3(2, 128), 128>>>(b0, 260, 252, W[8], W[9], nullptr, b1);
    // K5: b1 -> b0 [128,64,1255]
    { int total = 128 * 1255; k_up5<<<(total + 127) / 128, 128>>>(b1, W[10], W[11], W[12], b0); }
    // K6: b0 -> out [128,5000,4]
    { int total = 128 * 5000; k_up4<<<(total + 127) / 128, 128>>>(b0, W[13], W[14], out); }
}

// round 3
// speedup vs baseline: 2.6879x; 1.6515x over previous
#include <cuda_runtime.h>

// ---------------------------------------------------------------------------
// ECGSegMCULBit fused pipeline, round 3: same 6-kernel fusion as round 2 but
// with channel-parallel work distribution (warp/lane splits). All reduction
// reorders are exact in fp32 (operands are multiples of 1/64 or 1/4096,
// bounded), so results stay bit-identical to the reference.
// ---------------------------------------------------------------------------

#define DEVFN __device__ __forceinline__

__device__ float g_buf0[128u * 64u * 1255u];
__device__ float g_buf1[128u * 64u * 1255u];

DEVFN float lbitf(float x) { return rintf(__fmul_rn(x, 64.0f)) * 0.015625f; }

DEVFN float tanh_xla(float x) {
    const float kClamp = 7.99881172180175781f;
    float ax = fabsf(x);
    float xc = fminf(fmaxf(x, -kClamp), kClamp);
    float x2 = __fmul_rn(xc, xc);
    float p = -2.76076847742355e-16f;
    p = __fmaf_rn(x2, p, 2.00018790482477e-13f);
    p = __fmaf_rn(x2, p, -8.60467152213735e-11f);
    p = __fmaf_rn(x2, p, 5.12229709037114e-08f);
    p = __fmaf_rn(x2, p, 1.48572235717979e-05f);
    p = __fmaf_rn(x2, p, 6.37261928875436e-04f);
    p = __fmaf_rn(x2, p, 4.89352455891786e-03f);
    p = __fmul_rn(xc, p);
    float q = 1.19825839466702e-06f;
    q = __fmaf_rn(x2, q, 1.18534705686654e-04f);
    q = __fmaf_rn(x2, q, 2.26843463243900e-03f);
    q = __fmaf_rn(x2, q, 4.89352518554385e-03f);
    float r = __fdiv_rn(p, q);
    return (ax < 0.0004f) ? x : r;
}

DEVFN float lbit_tanh(float x) { return lbitf(tanh_xla(x)); }

DEVFN float smax_poly(float vmax, float v) {
    float d  = __fsub_rn(vmax, v);
    float d2 = __fmul_rn(__fmul_rn(d, d), 0.5f);
    float d3 = __fdiv_rn(__fmul_rn(d2, d), 3.0f);
    float d4 = __fmul_rn(__fmul_rn(d3, d), 0.25f);
    float den = __fadd_rn(__fadd_rn(__fadd_rn(__fadd_rn(1.0f, d), d2), d3), d4);
    return lbitf(__fdiv_rn(1.0f, den));
}

DEVFN float warp_max(float v) {
#pragma unroll
    for (int s = 16; s > 0; s >>= 1) v = fmaxf(v, __shfl_xor_sync(0xffffffffu, v, s));
    return v;
}
DEVFN float warp_sum(float v) {  // exact: all summed values are multiples of 1/64 etc.
#pragma unroll
    for (int s = 16; s > 0; s >>= 1) v = __fadd_rn(v, __shfl_xor_sync(0xffffffffu, v, s));
    return v;
}

// ---------------------------------------------------------------------------
// K1: pad(236,100) + /8 + lbit + avgpool(4,4) + lbit + qconv(12->4,k1,nonbin)
// ---------------------------------------------------------------------------
__global__ void k_head(const float* __restrict__ x, const float* __restrict__ w1,
                       float* __restrict__ out) {
    const int Lout = 1334, Lin = 5000;
    __shared__ float sw[48];
    if (threadIdx.x < 48) sw[threadIdx.x] = lbit_tanh(w1[threadIdx.x]);
    __syncthreads();
    int idx = blockIdx.x * blockDim.x + threadIdx.x;
    if (idx >= 128 * Lout) return;
    int pos = idx % Lout;
    int b = idx / Lout;
    float t[12];
#pragma unroll
    for (int c = 0; c < 12; c++) {
        const float* xp = x + ((size_t)b * 12 + c) * Lin;
        float s = 0.0f;
#pragma unroll
        for (int u = 0; u < 4; u++) {
            int sp = 4 * pos + u - 236;
            float v = 0.0f;
            if (sp >= 0 && sp < Lin) v = lbitf(__fmul_rn(xp[sp], 0.125f));
            s = __fadd_rn(s, v);
        }
        t[c] = lbit_tanh(lbitf(__fmul_rn(s, 0.25f)));
    }
#pragma unroll
    for (int o = 0; o < 4; o++) {
        float acc = 0.0f;
#pragma unroll
        for (int c = 0; c < 12; c++) acc = __fmaf_rn(sw[o * 12 + c], t[c], acc);
        out[((size_t)b * 4 + o) * Lout + pos] = lbitf(acc);
    }
}

// ---------------------------------------------------------------------------
// K2/K3/K4: qconv(4->4,k3) + qconv(4->64,k3,bin) + avgpool(PW,PS) + softmax
//           [+ qconv(64->4,k1,bin) if TAIL]
// Block: 256 threads = 8 warps; warp w owns output position j0+w.
// Lane l owns channels l and l+32.
// ---------------------------------------------------------------------------
template <int PW, int PS, bool TAIL>
__global__ __launch_bounds__(256)
void k_mid(const float* __restrict__ in, int Lin, int Lout,
           const float* __restrict__ w2, const float* __restrict__ w3,
           const float* __restrict__ wt, float* __restrict__ out) {
    const int POSB = 8;
    const int NT2 = PS * (POSB - 1) + PW + 2;
    const int NA  = NT2 + 2;
    __shared__ float sxa[4 * NA];
    __shared__ float st2[4 * NT2];
    __shared__ float sw2[48];
    __shared__ float sw3[64 * 4 * 3];
    __shared__ float swt[256];

    int b = blockIdx.y;
    int j0 = blockIdx.x * POSB;
    int base = PS * j0;
    int tid = threadIdx.x;

    for (int t = tid; t < 48; t += 256) sw2[t] = lbit_tanh(w2[t]);
    for (int t = tid; t < 64 * 4 * 3; t += 256) sw3[t] = (w3[t] >= 0.0f) ? 1.0f : -1.0f;
    if (TAIL)
        for (int t = tid; t < 256; t += 256) swt[t] = (wt[t] >= 0.0f) ? 1.0f : -1.0f;

    for (int t = tid; t < 4 * NA; t += 256) {
        int i = t / NA, p = t % NA;
        int g = base + p;
        sxa[t] = (g < Lin) ? lbit_tanh(in[((size_t)b * 4 + i) * Lin + g]) : 0.0f;
    }
    __syncthreads();

    // conv2 (4->4,k3) + lbit + tanh
    for (int t = tid; t < 4 * NT2; t += 256) {
        int q = t >> 2, o = t & 3;
        float acc = 0.0f;
#pragma unroll
        for (int i = 0; i < 4; i++)
#pragma unroll
            for (int k = 0; k < 3; k++)
                acc = __fmaf_rn(sw2[(o * 4 + i) * 3 + k], sxa[i * NA + q + k], acc);
        st2[o * NT2 + q] = lbit_tanh(lbitf(acc));
    }
    __syncthreads();

    int warp = tid >> 5;
    int lane = tid & 31;
    int j = j0 + warp;
    if (j >= Lout) return;

    // window of conv3 inputs for this position (broadcast reads)
    float xr[4][PW + 2];
#pragma unroll
    for (int i = 0; i < 4; i++)
#pragma unroll
        for (int w = 0; w < PW + 2; w++) xr[i][w] = st2[i * NT2 + PS * warp + w];

    float v[2], lmax;
#pragma unroll
    for (int h = 0; h < 2; h++) {
        int c = lane + 32 * h;
        float psum = 0.0f;
#pragma unroll
        for (int u = 0; u < PW; u++) {
            float acc = 0.0f;
#pragma unroll
            for (int i = 0; i < 4; i++)
#pragma unroll
                for (int k = 0; k < 3; k++)
                    acc = __fmaf_rn(sw3[(c * 4 + i) * 3 + k], xr[i][u + k], acc);
            psum = __fadd_rn(psum, lbitf(acc));
        }
        v[h] = lbitf(__fdiv_rn(psum, (float)PW));
    }
    lmax = fmaxf(v[0], v[1]);
    float vmax = warp_max(lmax);

    float o0 = smax_poly(vmax, v[0]);
    float o1 = smax_poly(vmax, v[1]);
    float sum = warp_sum(__fadd_rn(o0, o1));

    if (TAIL) {
        float tv0 = lbit_tanh(lbitf(__fdiv_rn(o0, sum)));
        float tv1 = lbit_tanh(lbitf(__fdiv_rn(o1, sum)));
#pragma unroll
        for (int o = 0; o < 4; o++) {
            float part = __fadd_rn(__fmul_rn(swt[o * 64 + lane], tv0),
                                   __fmul_rn(swt[o * 64 + lane + 32], tv1));
            float s = warp_sum(part);
            if (lane == 0) out[((size_t)b * 4 + o) * Lout + j] = lbitf(s);
        }
    } else {
        out[((size_t)b * 64 + lane) * Lout + j]        = lbitf(__fdiv_rn(o0, sum));
        out[((size_t)b * 64 + lane + 32) * Lout + j]   = lbitf(__fdiv_rn(o1, sum));
    }
}

// ---------------------------------------------------------------------------
// K5: upsample(x5) + qconv(64->8,bin) + qconv(8->8) + qconv(8->64,bin) + softmax
// in:[128,64,252] -> out:[128,64,1255]
// Block: 256 thr = 8 warps; lane = position (32/block), warp = channel group.
// ---------------------------------------------------------------------------
__global__ __launch_bounds__(256)
void k_up5(const float* __restrict__ in, const float* __restrict__ w1,
           const float* __restrict__ w2, const float* __restrict__ w3,
           float* __restrict__ out) {
    const int n = 252, Lout = 1255;
    __shared__ float sb1[512], sw2s[64], sb3[512];
    __shared__ float st[64 * 32];   // tanh(lerp) values [c][pos]
    __shared__ float s2[8 * 32];    // t2 values [o][pos]
    __shared__ float red[8 * 32];   // reductions

    int tid = threadIdx.x;
    for (int t = tid; t < 512; t += 256) sb1[t] = (w1[t] >= 0.0f) ? 1.0f : -1.0f;
    for (int t = tid; t < 64;  t += 256) sw2s[t] = lbit_tanh(w2[t]);
    for (int t = tid; t < 512; t += 256) sb3[t] = (w3[t] >= 0.0f) ? 1.0f : -1.0f;

    int lane = tid & 31;
    int cg   = tid >> 5;
    int b = blockIdx.y;
    int pos = blockIdx.x * 32 + lane;
    int cpos = min(pos, Lout - 1);  // clamp for safe reads; writes guarded

    int i = cpos + 2;
    float fi = __fadd_rn((float)i, 0.5f);
    float src = fmaxf(__fsub_rn(__fdiv_rn(fi, 5.0f), 0.5f), 0.0f);
    int i0 = (int)floorf(src);
    int i1 = min(i0 + 1, n - 1);
    float w = __fsub_rn(src, (float)i0);
    float w0 = __fsub_rn(1.0f, w);

    __syncthreads();

    const float* ip = in + (size_t)b * 64 * n;
#pragma unroll
    for (int cc = 0; cc < 8; cc++) {
        int c = cg * 8 + cc;
        float x0 = lbitf(ip[(size_t)c * n + i0]);
        float x1 = lbitf(ip[(size_t)c * n + i1]);
        float val = lbitf(__fadd_rn(__fmul_rn(x0, w0), __fmul_rn(x1, w)));
        st[c * 32 + lane] = lbit_tanh(val);
    }
    __syncthreads();

    // conv1 64->8 (bin): thread (o=cg, lane=pos)
    {
        float acc = 0.0f;
#pragma unroll
        for (int c = 0; c < 64; c++) acc = __fmaf_rn(sb1[cg * 64 + c], st[c * 32 + lane], acc);
        red[cg * 32 + lane] = lbit_tanh(lbitf(acc));   // t1
    }
    __syncthreads();
    // conv2 8->8: thread (o=cg, lane=pos)
    {
        float acc = 0.0f;
#pragma unroll
        for (int k = 0; k < 8; k++) acc = __fmaf_rn(sw2s[cg * 8 + k], red[k * 32 + lane], acc);
        s2[cg * 32 + lane] = lbit_tanh(lbitf(acc));    // t2
    }
    __syncthreads();

    // conv3 8->64 (bin) + softmax; thread handles 8 channels
    float v[8];
    float lmax = -3.0e38f;
#pragma unroll
    for (int cc = 0; cc < 8; cc++) {
        int c = cg * 8 + cc;
        float acc = 0.0f;
#pragma unroll
        for (int k = 0; k < 8; k++) acc = __fmaf_rn(sb3[c * 8 + k], s2[k * 32 + lane], acc);
        v[cc] = lbitf(acc);
        lmax = fmaxf(lmax, v[cc]);
    }
    red[cg * 32 + lane] = lmax;
    __syncthreads();
    float vmax = red[0 * 32 + lane];
#pragma unroll
    for (int g = 1; g < 8; g++) vmax = fmaxf(vmax, red[g * 32 + lane]);
    __syncthreads();

    float lsum = 0.0f;
#pragma unroll
    for (int cc = 0; cc < 8; cc++) {
        float o = smax_poly(vmax, v[cc]);
        v[cc] = o;
        lsum = __fadd_rn(lsum, o);
    }
    red[cg * 32 + lane] = lsum;
    __syncthreads();
    float sum = red[0 * 32 + lane];
#pragma unroll
    for (int g = 1; g < 8; g++) sum = __fadd_rn(sum, red[g * 32 + lane]);

    if (pos < Lout) {
        float* op = out + (size_t)b * 64 * Lout + pos;
#pragma unroll
        for (int cc = 0; cc < 8; cc++)
            op[(size_t)(cg * 8 + cc) * Lout] = lbitf(__fdiv_rn(v[cc], sum));
    }
}

// ---------------------------------------------------------------------------
// K6: upsample(x4) + qconv(64->8,bin) + qconv(8->4) + crop + transpose
// Block: 128 thr = 4 warps; lane = position (32/block), warp = channel quarter.
// ---------------------------------------------------------------------------
__global__ __launch_bounds__(128)
void k_up4(const float* __restrict__ in, const float* __restrict__ w4,
           const float* __restrict__ w5, float* __restrict__ out) {
    const int n = 1255;
    __shared__ float sb4[512], sw5[32];
    __shared__ float hp[4 * 8 * 32];  // partial h [sub][o][pos]

    int tid = threadIdx.x;
    for (int t = tid; t < 512; t += 128) sb4[t] = (w4[t] >= 0.0f) ? 1.0f : -1.0f;
    if (tid < 32) sw5[tid] = lbit_tanh(w5[tid]);

    int lane = tid & 31;
    int sub  = tid >> 5;
    int b = blockIdx.y;
    int pos = blockIdx.x * 32 + lane;
    int cpos = min(pos, 4999);

    int i = cpos + 18;
    float fi = __fadd_rn((float)i, 0.5f);
    float src = fmaxf(__fsub_rn(__fdiv_rn(fi, 4.0f), 0.5f), 0.0f);
    int i0 = (int)floorf(src);
    int i1 = min(i0 + 1, n - 1);
    float w = __fsub_rn(src, (float)i0);
    float w0 = __fsub_rn(1.0f, w);

    __syncthreads();

    float h[8];
#pragma unroll
    for (int o = 0; o < 8; o++) h[o] = 0.0f;
    const float* ip = in + (size_t)b * 64 * n;
#pragma unroll
    for (int cc = 0; cc < 16; cc++) {
        int c = sub * 16 + cc;
        float x0 = lbitf(ip[(size_t)c * n + i0]);
        float x1 = lbitf(ip[(size_t)c * n + i1]);
        float val = lbitf(__fadd_rn(__fmul_rn(x0, w0), __fmul_rn(x1, w)));
        float tv = lbit_tanh(val);
#pragma unroll
        for (int o = 0; o < 8; o++) h[o] = __fmaf_rn(sb4[o * 64 + c], tv, h[o]);
    }
#pragma unroll
    for (int o = 0; o < 8; o++) hp[(sub * 8 + o) * 32 + lane] = h[o];
    __syncthreads();

    if (sub == 0 && pos < 5000) {
        float t4[8];
#pragma unroll
        for (int o = 0; o < 8; o++) {
            float s = __fadd_rn(__fadd_rn(hp[o * 32 + lane], hp[(8 + o) * 32 + lane]),
                                __fadd_rn(hp[(16 + o) * 32 + lane], hp[(24 + o) * 32 + lane]));
            t4[o] = lbit_tanh(lbitf(s));
        }
        float rr[4];
#pragma unroll
        for (int o = 0; o < 4; o++) {
            float acc = 0.0f;
#pragma unroll
            for (int k = 0; k < 8; k++) acc = __fmaf_rn(sw5[o * 8 + k], t4[k], acc);
            rr[o] = lbitf(acc);
        }
        float4* o4 = (float4*)(out + ((size_t)b * 5000 + pos) * 4);
        *o4 = make_float4(rr[0], rr[1], rr[2], rr[3]);
    }
}

// ---------------------------------------------------------------------------
// Host launcher.
// ---------------------------------------------------------------------------
extern "C" void kernel_launch(void* const* d_in, const int* in_sizes, int n_in,
                              void* d_out, int out_size) {
    (void)in_sizes; (void)n_in; (void)out_size;
    float *b0, *b1;
    cudaGetSymbolAddress((void**)&b0, g_buf0);
    cudaGetSymbolAddress((void**)&b1, g_buf1);

    const float* W[15];
    for (int i = 0; i < 15; i++) W[i] = (const float*)d_in[i];
    float* out = (float*)d_out;

    { int total = 128 * 1334; k_head<<<(total + 255) / 256, 256>>>(W[0], W[1], b0); }
    k_mid<5, 5, true ><<<dim3(34, 128), 256>>>(b0, 1334, 266, W[2], W[3], W[4], b1);
    k_mid<3, 1, true ><<<dim3(33, 128), 256>>>(b1, 266, 260, W[5], W[6], W[7], b0);
    k_mid<5, 1, false><<<dim3(32, 128), 256>>>(b0, 260, 252, W[8], W[9], nullptr, b1);
    k_up5<<<dim3(40, 128), 256>>>(b1, W[10], W[11], W[12], b0);
    k_up4<<<dim3(157, 128), 128>>>(b0, W[13], W[14], out);
}

// round 4
// speedup vs baseline: 3.8250x; 1.4231x over previous
#include <cuda_runtime.h>

// ---------------------------------------------------------------------------
// ECGSegMCULBit fused pipeline, round 4: round-3 structure + LUTs.
// Every lbit_tanh input is (or is first lbit'd to) a multiple of 1/64, so
// lbit_tanh(lbitf(y)) == TANH_LUT[rint(y*64)] (saturates exactly to +-1 past
// |x|=8). smax_poly's d = vmax-v is an exact multiple of 1/64 in [0,24], so
// it is SMAX_LUT[rint(d*64)]. LUT entries are computed by an init kernel with
// the exact original intrinsic sequences -> results stay bit-identical.
// ---------------------------------------------------------------------------

#define DEVFN __device__ __forceinline__

__device__ float g_buf0[128u * 64u * 1255u];
__device__ float g_buf1[128u * 64u * 1255u];
__device__ float g_tanh_lut[1025];   // idx = rint(x*64)+512, x in [-8,8]
__device__ float g_smax_lut[2049];   // idx = rint(d*64),     d in [0,32]

DEVFN float lbitf(float x) { return rintf(__fmul_rn(x, 64.0f)) * 0.015625f; }

DEVFN float tanh_xla(float x) {
    const float kClamp = 7.99881172180175781f;
    float ax = fabsf(x);
    float xc = fminf(fmaxf(x, -kClamp), kClamp);
    float x2 = __fmul_rn(xc, xc);
    float p = -2.76076847742355e-16f;
    p = __fmaf_rn(x2, p, 2.00018790482477e-13f);
    p = __fmaf_rn(x2, p, -8.60467152213735e-11f);
    p = __fmaf_rn(x2, p, 5.12229709037114e-08f);
    p = __fmaf_rn(x2, p, 1.48572235717979e-05f);
    p = __fmaf_rn(x2, p, 6.37261928875436e-04f);
    p = __fmaf_rn(x2, p, 4.89352455891786e-03f);
    p = __fmul_rn(xc, p);
    float q = 1.19825839466702e-06f;
    q = __fmaf_rn(x2, q, 1.18534705686654e-04f);
    q = __fmaf_rn(x2, q, 2.26843463243900e-03f);
    q = __fmaf_rn(x2, q, 4.89352518554385e-03f);
    float r = __fdiv_rn(p, q);
    return (ax < 0.0004f) ? x : r;
}

DEVFN float lbit_tanh(float x) { return lbitf(tanh_xla(x)); }  // weights only

DEVFN float smax_poly_d(float d) {
    float d2 = __fmul_rn(__fmul_rn(d, d), 0.5f);
    float d3 = __fdiv_rn(__fmul_rn(d2, d), 3.0f);
    float d4 = __fmul_rn(__fmul_rn(d3, d), 0.25f);
    float den = __fadd_rn(__fadd_rn(__fadd_rn(__fadd_rn(1.0f, d), d2), d3), d4);
    return lbitf(__fdiv_rn(1.0f, den));
}

// lbit_tanh(lbitf(y)) via LUT. y arbitrary; y*64 rounding == lbit's rounding.
DEVFN float ltanh(float y) {
    int i = __float2int_rn(__fmul_rn(y, 64.0f));
    i = min(max(i, -512), 512);
    return __ldg(&g_tanh_lut[i + 512]);
}
// smax_poly via LUT; vmax - v exact multiple of 1/64, d*64 <= 2048 always.
DEVFN float lsmax(float vmax, float v) {
    int i = __float2int_rn(__fmul_rn(__fsub_rn(vmax, v), 64.0f));
    i = min(i, 2048);
    return __ldg(&g_smax_lut[i]);
}

__global__ void k_init_luts() {
    int i = blockIdx.x * blockDim.x + threadIdx.x;
    if (i < 1025) g_tanh_lut[i] = lbitf(tanh_xla((float)(i - 512) * 0.015625f));
    if (i < 2049) g_smax_lut[i] = smax_poly_d((float)i * 0.015625f);
}

DEVFN float warp_max(float v) {
#pragma unroll
    for (int s = 16; s > 0; s >>= 1) v = fmaxf(v, __shfl_xor_sync(0xffffffffu, v, s));
    return v;
}
DEVFN float warp_sum(float v) {  // exact: summands are multiples of 1/64
#pragma unroll
    for (int s = 16; s > 0; s >>= 1) v = __fadd_rn(v, __shfl_xor_sync(0xffffffffu, v, s));
    return v;
}

// ---------------------------------------------------------------------------
// K1: pad + /8 + lbit + avgpool(4,4) + lbit + qconv(12->4,k1)
// ---------------------------------------------------------------------------
__global__ void k_head(const float* __restrict__ x, const float* __restrict__ w1,
                       float* __restrict__ out) {
    const int Lout = 1334, Lin = 5000;
    __shared__ float sw[48];
    if (threadIdx.x < 48) sw[threadIdx.x] = lbit_tanh(w1[threadIdx.x]);
    __syncthreads();
    int idx = blockIdx.x * blockDim.x + threadIdx.x;
    if (idx >= 128 * Lout) return;
    int pos = idx % Lout;
    int b = idx / Lout;
    float t[12];
#pragma unroll
    for (int c = 0; c < 12; c++) {
        const float* xp = x + ((size_t)b * 12 + c) * Lin;
        float s = 0.0f;
#pragma unroll
        for (int u = 0; u < 4; u++) {
            int sp = 4 * pos + u - 236;
            float v = 0.0f;
            if (sp >= 0 && sp < Lin) v = lbitf(__fmul_rn(xp[sp], 0.125f));
            s = __fadd_rn(s, v);
        }
        t[c] = ltanh(__fmul_rn(s, 0.25f));   // == lbit_tanh(lbitf(s*0.25))
    }
#pragma unroll
    for (int o = 0; o < 4; o++) {
        float acc = 0.0f;
#pragma unroll
        for (int c = 0; c < 12; c++) acc = __fmaf_rn(sw[o * 12 + c], t[c], acc);
        out[((size_t)b * 4 + o) * Lout + pos] = lbitf(acc);
    }
}

// ---------------------------------------------------------------------------
// K2/K3/K4 fused mids. Warp per position; lane owns channels l, l+32.
// ---------------------------------------------------------------------------
template <int PW, int PS, bool TAIL>
__global__ __launch_bounds__(256)
void k_mid(const float* __restrict__ in, int Lin, int Lout,
           const float* __restrict__ w2, const float* __restrict__ w3,
           const float* __restrict__ wt, float* __restrict__ out) {
    const int POSB = 8;
    const int NT2 = PS * (POSB - 1) + PW + 2;
    const int NA  = NT2 + 2;
    __shared__ float sxa[4 * NA];
    __shared__ float st2[4 * NT2];
    __shared__ float sw2[48];
    __shared__ float sw3[64 * 4 * 3];
    __shared__ float swt[256];

    int b = blockIdx.y;
    int j0 = blockIdx.x * POSB;
    int base = PS * j0;
    int tid = threadIdx.x;

    for (int t = tid; t < 48; t += 256) sw2[t] = lbit_tanh(w2[t]);
    for (int t = tid; t < 64 * 4 * 3; t += 256) sw3[t] = (w3[t] >= 0.0f) ? 1.0f : -1.0f;
    if (TAIL)
        for (int t = tid; t < 256; t += 256) swt[t] = (wt[t] >= 0.0f) ? 1.0f : -1.0f;

    for (int t = tid; t < 4 * NA; t += 256) {
        int i = t / NA, p = t % NA;
        int g = base + p;
        sxa[t] = (g < Lin) ? ltanh(in[((size_t)b * 4 + i) * Lin + g]) : 0.0f;
    }
    __syncthreads();

    for (int t = tid; t < 4 * NT2; t += 256) {
        int q = t >> 2, o = t & 3;
        float acc = 0.0f;
#pragma unroll
        for (int i = 0; i < 4; i++)
#pragma unroll
            for (int k = 0; k < 3; k++)
                acc = __fmaf_rn(sw2[(o * 4 + i) * 3 + k], sxa[i * NA + q + k], acc);
        st2[o * NT2 + q] = ltanh(acc);      // == lbit_tanh(lbitf(acc))
    }
    __syncthreads();

    int warp = tid >> 5;
    int lane = tid & 31;
    int j = j0 + warp;
    if (j >= Lout) return;

    float xr[4][PW + 2];
#pragma unroll
    for (int i = 0; i < 4; i++)
#pragma unroll
        for (int w = 0; w < PW + 2; w++) xr[i][w] = st2[i * NT2 + PS * warp + w];

    float v[2];
#pragma unroll
    for (int h = 0; h < 2; h++) {
        int c = lane + 32 * h;
        float psum = 0.0f;
#pragma unroll
        for (int u = 0; u < PW; u++) {
            float acc = 0.0f;
#pragma unroll
            for (int i = 0; i < 4; i++)
#pragma unroll
                for (int k = 0; k < 3; k++)
                    acc = __fmaf_rn(sw3[(c * 4 + i) * 3 + k], xr[i][u + k], acc);
            psum = __fadd_rn(psum, lbitf(acc));
        }
        v[h] = lbitf(__fdiv_rn(psum, (float)PW));
    }
    float vmax = warp_max(fmaxf(v[0], v[1]));

    float o0 = lsmax(vmax, v[0]);
    float o1 = lsmax(vmax, v[1]);
    float sum = warp_sum(__fadd_rn(o0, o1));

    if (TAIL) {
        float tv0 = ltanh(__fdiv_rn(o0, sum));
        float tv1 = ltanh(__fdiv_rn(o1, sum));
#pragma unroll
        for (int o = 0; o < 4; o++) {
            float part = __fadd_rn(__fmul_rn(swt[o * 64 + lane], tv0),
                                   __fmul_rn(swt[o * 64 + lane + 32], tv1));
            float s = warp_sum(part);
            if (lane == 0) out[((size_t)b * 4 + o) * Lout + j] = lbitf(s);
        }
    } else {
        out[((size_t)b * 64 + lane) * Lout + j]      = lbitf(__fdiv_rn(o0, sum));
        out[((size_t)b * 64 + lane + 32) * Lout + j] = lbitf(__fdiv_rn(o1, sum));
    }
}

// ---------------------------------------------------------------------------
// K5: upsample(x5) + conv(64->8,bin) + conv(8->8) + conv(8->64,bin) + softmax
// ---------------------------------------------------------------------------
__global__ __launch_bounds__(256)
void k_up5(const float* __restrict__ in, const float* __restrict__ w1,
           const float* __restrict__ w2, const float* __restrict__ w3,
           float* __restrict__ out) {
    const int n = 252, Lout = 1255;
    __shared__ float sb1[512], sw2s[64], sb3[512];
    __shared__ float st[64 * 32];
    __shared__ float s2[8 * 32];
    __shared__ float red[8 * 32];

    int tid = threadIdx.x;
    for (int t = tid; t < 512; t += 256) sb1[t] = (w1[t] >= 0.0f) ? 1.0f : -1.0f;
    for (int t = tid; t < 64;  t += 256) sw2s[t] = lbit_tanh(w2[t]);
    for (int t = tid; t < 512; t += 256) sb3[t] = (w3[t] >= 0.0f) ? 1.0f : -1.0f;

    int lane = tid & 31;
    int cg   = tid >> 5;
    int b = blockIdx.y;
    int pos = blockIdx.x * 32 + lane;
    int cpos = min(pos, Lout - 1);

    int i = cpos + 2;
    float fi = __fadd_rn((float)i, 0.5f);
    float src = fmaxf(__fsub_rn(__fdiv_rn(fi, 5.0f), 0.5f), 0.0f);
    int i0 = (int)floorf(src);
    int i1 = min(i0 + 1, n - 1);
    float w = __fsub_rn(src, (float)i0);
    float w0 = __fsub_rn(1.0f, w);

    __syncthreads();

    const float* ip = in + (size_t)b * 64 * n;
#pragma unroll
    for (int cc = 0; cc < 8; cc++) {
        int c = cg * 8 + cc;
        float x0 = lbitf(ip[(size_t)c * n + i0]);
        float x1 = lbitf(ip[(size_t)c * n + i1]);
        // ltanh(lerp) == lbit_tanh(lbitf(lerp))
        st[c * 32 + lane] = ltanh(__fadd_rn(__fmul_rn(x0, w0), __fmul_rn(x1, w)));
    }
    __syncthreads();

    {
        float acc = 0.0f;
#pragma unroll
        for (int c = 0; c < 64; c++) acc = __fmaf_rn(sb1[cg * 64 + c], st[c * 32 + lane], acc);
        red[cg * 32 + lane] = ltanh(acc);
    }
    __syncthreads();
    {
        float acc = 0.0f;
#pragma unroll
        for (int k = 0; k < 8; k++) acc = __fmaf_rn(sw2s[cg * 8 + k], red[k * 32 + lane], acc);
        s2[cg * 32 + lane] = ltanh(acc);
    }
    __syncthreads();

    float v[8];
    float lmax = -3.0e38f;
#pragma unroll
    for (int cc = 0; cc < 8; cc++) {
        int c = cg * 8 + cc;
        float acc = 0.0f;
#pragma unroll
        for (int k = 0; k < 8; k++) acc = __fmaf_rn(sb3[c * 8 + k], s2[k * 32 + lane], acc);
        v[cc] = lbitf(acc);
        lmax = fmaxf(lmax, v[cc]);
    }
    red[cg * 32 + lane] = lmax;
    __syncthreads();
    float vmax = red[0 * 32 + lane];
#pragma unroll
    for (int g = 1; g < 8; g++) vmax = fmaxf(vmax, red[g * 32 + lane]);
    __syncthreads();

    float lsum = 0.0f;
#pragma unroll
    for (int cc = 0; cc < 8; cc++) {
        float o = lsmax(vmax, v[cc]);
        v[cc] = o;
        lsum = __fadd_rn(lsum, o);
    }
    red[cg * 32 + lane] = lsum;
    __syncthreads();
    float sum = red[0 * 32 + lane];
#pragma unroll
    for (int g = 1; g < 8; g++) sum = __fadd_rn(sum, red[g * 32 + lane]);

    if (pos < Lout) {
        float* op = out + (size_t)b * 64 * Lout + pos;
#pragma unroll
        for (int cc = 0; cc < 8; cc++)
            op[(size_t)(cg * 8 + cc) * Lout] = lbitf(__fdiv_rn(v[cc], sum));
    }
}

// ---------------------------------------------------------------------------
// K6: upsample(x4) + conv(64->8,bin) + conv(8->4) + crop + transpose
// ---------------------------------------------------------------------------
__global__ __launch_bounds__(128)
void k_up4(const float* __restrict__ in, const float* __restrict__ w4,
           const float* __restrict__ w5, float* __restrict__ out) {
    const int n = 1255;
    __shared__ float sb4[512], sw5[32];
    __shared__ float hp[4 * 8 * 32];

    int tid = threadIdx.x;
    for (int t = tid; t < 512; t += 128) sb4[t] = (w4[t] >= 0.0f) ? 1.0f : -1.0f;
    if (tid < 32) sw5[tid] = lbit_tanh(w5[tid]);

    int lane = tid & 31;
    int sub  = tid >> 5;
    int b = blockIdx.y;
    int pos = blockIdx.x * 32 + lane;
    int cpos = min(pos, 4999);

    int i = cpos + 18;
    float fi = __fadd_rn((float)i, 0.5f);
    float src = fmaxf(__fsub_rn(__fdiv_rn(fi, 4.0f), 0.5f), 0.0f);
    int i0 = (int)floorf(src);
    int i1 = min(i0 + 1, n - 1);
    float w = __fsub_rn(src, (float)i0);
    float w0 = __fsub_rn(1.0f, w);

    __syncthreads();

    float h[8];
#pragma unroll
    for (int o = 0; o < 8; o++) h[o] = 0.0f;
    const float* ip = in + (size_t)b * 64 * n;
#pragma unroll
    for (int cc = 0; cc < 16; cc++) {
        int c = sub * 16 + cc;
        float x0 = lbitf(ip[(size_t)c * n + i0]);
        float x1 = lbitf(ip[(size_t)c * n + i1]);
        float tv = ltanh(__fadd_rn(__fmul_rn(x0, w0), __fmul_rn(x1, w)));
#pragma unroll
        for (int o = 0; o < 8; o++) h[o] = __fmaf_rn(sb4[o * 64 + c], tv, h[o]);
    }
#pragma unroll
    for (int o = 0; o < 8; o++) hp[(sub * 8 + o) * 32 + lane] = h[o];
    __syncthreads();

    if (sub == 0 && pos < 5000) {
        float t4[8];
#pragma unroll
        for (int o = 0; o < 8; o++) {
            float s = __fadd_rn(__fadd_rn(hp[o * 32 + lane], hp[(8 + o) * 32 + lane]),
                                __fadd_rn(hp[(16 + o) * 32 + lane], hp[(24 + o) * 32 + lane]));
            t4[o] = ltanh(s);
        }
        float rr[4];
#pragma unroll
        for (int o = 0; o < 4; o++) {
            float acc = 0.0f;
#pragma unroll
            for (int k = 0; k < 8; k++) acc = __fmaf_rn(sw5[o * 8 + k], t4[k], acc);
            rr[o] = lbitf(acc);
        }
        float4* o4 = (float4*)(out + ((size_t)b * 5000 + pos) * 4);
        *o4 = make_float4(rr[0], rr[1], rr[2], rr[3]);
    }
}

// ---------------------------------------------------------------------------
// Host launcher.
// ---------------------------------------------------------------------------
extern "C" void kernel_launch(void* const* d_in, const int* in_sizes, int n_in,
                              void* d_out, int out_size) {
    (void)in_sizes; (void)n_in; (void)out_size;
    float *b0, *b1;
    cudaGetSymbolAddress((void**)&b0, g_buf0);
    cudaGetSymbolAddress((void**)&b1, g_buf1);

    const float* W[15];
    for (int i = 0; i < 15; i++) W[i] = (const float*)d_in[i];
    float* out = (float*)d_out;

    k_init_luts<<<9, 256>>>();
    { int total = 128 * 1334; k_head<<<(total + 255) / 256, 256>>>(W[0], W[1], b0); }
    k_mid<5, 5, true ><<<dim3(34, 128), 256>>>(b0, 1334, 266, W[2], W[3], W[4], b1);
    k_mid<3, 1, true ><<<dim3(33, 128), 256>>>(b1, 266, 260, W[5], W[6], W[7], b0);
    k_mid<5, 1, false><<<dim3(32, 128), 256>>>(b0, 260, 252, W[8], W[9], nullptr, b1);
    k_up5<<<dim3(40, 128), 256>>>(b1, W[10], W[11], W[12], b0);
    k_up4<<<dim3(157, 128), 128>>>(b0, W[13], W[14], out);
}

// round 5
// speedup vs baseline: 5.3917x; 1.4096x over previous
#include <cuda_runtime.h>

// ---------------------------------------------------------------------------
// ECGSegMCULBit fused pipeline, round 5: int8/dp4a arithmetic.
// All quantized activations are k/64 with k in [-64,64] (int8); binary weights
// are +-1 and tanh'd weights are a/64 (int8). Convolutions are exact integer
// dot products via dp4a; lbit after binary convs is an identity and tanh/softmax
// LUTs index directly off integer sums. Float ops retained only where the
// reference rounding matters (/PW, o/sum, lerp), using identical intrinsic
// sequences -> results stay bit-identical to the JAX reference.
// ---------------------------------------------------------------------------

#define DEVFN __device__ __forceinline__
typedef unsigned char uchar_t;

__device__ float g_buf0[128u * 64u * 1255u];
__device__ float g_buf1[128u * 64u * 1255u];
__device__ float g_tanh_f[1025];   // lbit_tanh(i/64), float
__device__ int   g_tanh_i[1025];   // same, *64 as int
__device__ int   g_smax_i[2049];   // lbit(1/poly(d))*64 as int, d = i/64

DEVFN float lbitf(float x) { return rintf(__fmul_rn(x, 64.0f)) * 0.015625f; }

DEVFN float tanh_xla(float x) {
    const float kClamp = 7.99881172180175781f;
    float ax = fabsf(x);
    float xc = fminf(fmaxf(x, -kClamp), kClamp);
    float x2 = __fmul_rn(xc, xc);
    float p = -2.76076847742355e-16f;
    p = __fmaf_rn(x2, p, 2.00018790482477e-13f);
    p = __fmaf_rn(x2, p, -8.60467152213735e-11f);
    p = __fmaf_rn(x2, p, 5.12229709037114e-08f);
    p = __fmaf_rn(x2, p, 1.48572235717979e-05f);
    p = __fmaf_rn(x2, p, 6.37261928875436e-04f);
    p = __fmaf_rn(x2, p, 4.89352455891786e-03f);
    p = __fmul_rn(xc, p);
    float q = 1.19825839466702e-06f;
    q = __fmaf_rn(x2, q, 1.18534705686654e-04f);
    q = __fmaf_rn(x2, q, 2.26843463243900e-03f);
    q = __fmaf_rn(x2, q, 4.89352518554385e-03f);
    float r = __fdiv_rn(p, q);
    return (ax < 0.0004f) ? x : r;
}

DEVFN float lbit_tanh(float x) { return lbitf(tanh_xla(x)); }  // weights only

DEVFN float smax_poly_d(float d) {
    float d2 = __fmul_rn(__fmul_rn(d, d), 0.5f);
    float d3 = __fdiv_rn(__fmul_rn(d2, d), 3.0f);
    float d4 = __fmul_rn(__fmul_rn(d3, d), 0.25f);
    float den = __fadd_rn(__fadd_rn(__fadd_rn(__fadd_rn(1.0f, d), d2), d3), d4);
    return lbitf(__fdiv_rn(1.0f, den));
}

DEVFN int tanh_idx(float y) {
    int i = __float2int_rn(__fmul_rn(y, 64.0f));
    return min(max(i, -512), 512) + 512;
}
DEVFN int   ltanh_i(float y) { return g_tanh_i[tanh_idx(y)]; }
DEVFN float ltanh_f(float y) { return g_tanh_f[tanh_idx(y)]; }
DEVFN int   tanh_of_int(int m) { return g_tanh_i[min(max(m, -512), 512) + 512]; }

DEVFN int dp4a(int a, int b, int c) {
    int d;
    asm("dp4a.s32.s32 %0, %1, %2, %3;" : "=r"(d) : "r"(a), "r"(b), "r"(c));
    return d;
}
DEVFN int pack4(int a, int b, int c, int d) {
    return (a & 255) | ((b & 255) << 8) | ((c & 255) << 16) | ((d & 255) << 24);
}
DEVFN int sgn_i(float v) { return (v >= 0.0f) ? 1 : -1; }
DEVFN int w_i(float v) { return __float2int_rn(__fmul_rn(lbit_tanh(v), 64.0f)); }

__global__ void k_init_luts() {
    int i = blockIdx.x * blockDim.x + threadIdx.x;
    if (i < 1025) {
        float v = lbitf(tanh_xla((float)(i - 512) * 0.015625f));
        g_tanh_f[i] = v;
        g_tanh_i[i] = __float2int_rn(__fmul_rn(v, 64.0f));
    }
    if (i < 2049)
        g_smax_i[i] = __float2int_rn(__fmul_rn(smax_poly_d((float)i * 0.015625f), 64.0f));
}

// ---------------------------------------------------------------------------
// K1: pad + /8 + lbit + avgpool(4,4) + lbit + qconv(12->4,k1)   (float path;
// input x is NOT quantized so lbitf on load is required here)
// ---------------------------------------------------------------------------
__global__ void k_head(const float* __restrict__ x, const float* __restrict__ w1,
                       float* __restrict__ out) {
    const int Lout = 1334, Lin = 5000;
    __shared__ float sw[48];
    if (threadIdx.x < 48) sw[threadIdx.x] = lbit_tanh(w1[threadIdx.x]);
    __syncthreads();
    int idx = blockIdx.x * blockDim.x + threadIdx.x;
    if (idx >= 128 * Lout) return;
    int pos = idx % Lout;
    int b = idx / Lout;
    float t[12];
#pragma unroll
    for (int c = 0; c < 12; c++) {
        const float* xp = x + ((size_t)b * 12 + c) * Lin;
        float s = 0.0f;
#pragma unroll
        for (int u = 0; u < 4; u++) {
            int sp = 4 * pos + u - 236;
            float v = 0.0f;
            if (sp >= 0 && sp < Lin) v = lbitf(__fmul_rn(xp[sp], 0.125f));
            s = __fadd_rn(s, v);
        }
        t[c] = ltanh_f(__fmul_rn(s, 0.25f));
    }
#pragma unroll
    for (int o = 0; o < 4; o++) {
        float acc = 0.0f;
#pragma unroll
        for (int c = 0; c < 12; c++) acc = __fmaf_rn(sw[o * 12 + c], t[c], acc);
        out[((size_t)b * 4 + o) * Lout + pos] = lbitf(acc);
    }
}

// ---------------------------------------------------------------------------
// K2/K3/K4: int8 path. conv2 (4->4,k3) dp4a; conv3 (4->64,k3,bin) dp4a computed
// ONCE per conv-position into smem; pool = int sums; softmax via int LUTs and
// redux ops; optional tail conv (64->4,bin) as int IMAD + redux.
// ---------------------------------------------------------------------------
template <int PW, int PS, int POSB, bool TAIL>
__global__ __launch_bounds__(256)
void k_mid(const float* __restrict__ in, int Lin, int Lout,
           const float* __restrict__ w2, const float* __restrict__ w3,
           const float* __restrict__ wt, float* __restrict__ out) {
    const int ITER = POSB / 8;
    const int NT3 = PS * (POSB - 1) + PW;         // conv3-out positions needed
    const int NT3P = (NT3 % 2 == 0) ? NT3 + 1 : NT3;  // odd stride, no bank conflict
    const int NT2 = NT3 + 2;                      // conv2-out positions needed
    const int NA  = NT2 + 2;                      // conv2-in positions needed
    __shared__ int sxaw[NA];        // packed 4 input channels per position
    __shared__ int st2w[NT2];       // packed 4 conv2-out channels per position
    __shared__ int sconv[64 * NT3P];
    __shared__ int w2p[12];         // [o*3+k] packed over i
    __shared__ int w3p[192];        // [c*3+k] packed signs over i
    __shared__ int swt[256];

    int b = blockIdx.y;
    int j0 = blockIdx.x * POSB;
    int base = PS * j0;
    int tid = threadIdx.x;
    uchar_t* sxab = (uchar_t*)sxaw;

    for (int t = tid; t < 12; t += 256) {
        int o = t / 3, k = t % 3;
        w2p[t] = pack4(w_i(w2[(o * 4 + 0) * 3 + k]), w_i(w2[(o * 4 + 1) * 3 + k]),
                       w_i(w2[(o * 4 + 2) * 3 + k]), w_i(w2[(o * 4 + 3) * 3 + k]));
    }
    for (int t = tid; t < 192; t += 256) {
        int c = t / 3, k = t % 3;
        w3p[t] = pack4(sgn_i(w3[(c * 4 + 0) * 3 + k]), sgn_i(w3[(c * 4 + 1) * 3 + k]),
                       sgn_i(w3[(c * 4 + 2) * 3 + k]), sgn_i(w3[(c * 4 + 3) * 3 + k]));
    }
    if (TAIL)
        for (int t = tid; t < 256; t += 256) swt[t] = sgn_i(wt[t]);

    // input is quantized (multiples of 1/64): lbitf identity; tanh via int LUT
    for (int t = tid; t < 4 * NA; t += 256) {
        int i = t / NA, p = t % NA;
        int g = base + p;
        int k = 0;
        if (g < Lin) k = ltanh_i(in[((size_t)b * 4 + i) * Lin + g]);
        sxab[p * 4 + i] = (uchar_t)k;
    }
    __syncthreads();

    // conv2: per position, 4 outputs, 3 dp4a each; output packed int8
    for (int q = tid; q < NT2; q += 256) {
        int word = 0;
#pragma unroll
        for (int o = 0; o < 4; o++) {
            int acc = 0;
#pragma unroll
            for (int k = 0; k < 3; k++) acc = dp4a(sxaw[q + k], w2p[o * 3 + k], acc);
            // acc/4096 is the float conv value; lbit index = rint(acc/64) RNE
            int idx = __float2int_rn(__fmul_rn((float)acc, 0.015625f));
            word |= (tanh_of_int(idx) & 255) << (8 * o);
        }
        st2w[q] = word;
    }
    __syncthreads();

    // conv3 (binary): integer sums, computed once per position
    for (int t = tid; t < 64 * NT3; t += 256) {
        int c = t / NT3, q = t % NT3;
        int acc = 0;
#pragma unroll
        for (int k = 0; k < 3; k++) acc = dp4a(st2w[q + k], w3p[c * 3 + k], acc);
        sconv[c * NT3P + q] = acc;   // value = acc/64, lbit identity
    }
    __syncthreads();

    int warp = tid >> 5;
    int lane = tid & 31;

#pragma unroll
    for (int it = 0; it < ITER; it++) {
        int wl = warp + 8 * it;
        int j = j0 + wl;
        if (j >= Lout) continue;
        int qb = PS * wl;

        int ps0 = 0, ps1 = 0;
#pragma unroll
        for (int u = 0; u < PW; u++) {
            ps0 += sconv[lane * NT3P + qb + u];
            ps1 += sconv[(lane + 32) * NT3P + qb + u];
        }
        // v = lbit(psum_f/PW); v*64 = rint(RN(psum_i/PW)) (power-of-2 scaling)
        int v0 = __float2int_rn(__fdiv_rn((float)ps0, (float)PW));
        int v1 = __float2int_rn(__fdiv_rn((float)ps1, (float)PW));
        int vmax = __reduce_max_sync(0xffffffffu, max(v0, v1));
        int o0 = g_smax_i[min(vmax - v0, 2048)];
        int o1 = g_smax_i[min(vmax - v1, 2048)];
        int sum = __reduce_add_sync(0xffffffffu, o0 + o1);
        float sf = __fmul_rn((float)sum, 0.015625f);

        if (TAIL) {
            float q0 = __fdiv_rn(__fmul_rn((float)o0, 0.015625f), sf);
            float q1 = __fdiv_rn(__fmul_rn((float)o1, 0.015625f), sf);
            int tv0 = ltanh_i(q0);
            int tv1 = ltanh_i(q1);
#pragma unroll
            for (int o = 0; o < 4; o++) {
                int part = swt[o * 64 + lane] * tv0 + swt[o * 64 + lane + 32] * tv1;
                int s = __reduce_add_sync(0xffffffffu, part);
                if (lane == 0)
                    out[((size_t)b * 4 + o) * Lout + j] = __fmul_rn((float)s, 0.015625f);
            }
        } else {
            out[((size_t)b * 64 + lane) * Lout + j] =
                lbitf(__fdiv_rn(__fmul_rn((float)o0, 0.015625f), sf));
            out[((size_t)b * 64 + lane + 32) * Lout + j] =
                lbitf(__fdiv_rn(__fmul_rn((float)o1, 0.015625f), sf));
        }
    }
}

// ---------------------------------------------------------------------------
// K5: upsample(x5) + conv(64->8,bin) + conv(8->8) + conv(8->64,bin) + softmax
// int8/dp4a path. Block: 256 thr; lane = position, warp = channel group.
// ---------------------------------------------------------------------------
__global__ __launch_bounds__(256)
void k_up5(const float* __restrict__ in, const float* __restrict__ w1,
           const float* __restrict__ w2, const float* __restrict__ w3,
           float* __restrict__ out) {
    const int n = 252, Lout = 1255;
    __shared__ int w1p[128];        // [o*16+g] signs packed over 4 channels
    __shared__ int w2p[16];         // [o*2+j]  tanh'd ints packed
    __shared__ int w3p[128];        // [c*2+j]  signs packed
    __shared__ int stp[16 * 32];    // packed lerp-tanh ints [g][pos]
    __shared__ uchar_t s1b[32 * 8]; // t1 bytes [pos][o]
    __shared__ uchar_t s2b[32 * 8]; // t2 bytes [pos][o]
    __shared__ int red[8 * 32];

    int tid = threadIdx.x;
    for (int t = tid; t < 128; t += 256) {
        int o = t >> 4, g = t & 15;
        w1p[t] = pack4(sgn_i(w1[o * 64 + 4 * g + 0]), sgn_i(w1[o * 64 + 4 * g + 1]),
                       sgn_i(w1[o * 64 + 4 * g + 2]), sgn_i(w1[o * 64 + 4 * g + 3]));
    }
    for (int t = tid; t < 16; t += 256) {
        int o = t >> 1, j = t & 1;
        w2p[t] = pack4(w_i(w2[o * 8 + 4 * j + 0]), w_i(w2[o * 8 + 4 * j + 1]),
                       w_i(w2[o * 8 + 4 * j + 2]), w_i(w2[o * 8 + 4 * j + 3]));
    }
    for (int t = tid; t < 128; t += 256) {
        int c = t >> 1, j = t & 1;
        w3p[t] = pack4(sgn_i(w3[c * 8 + 4 * j + 0]), sgn_i(w3[c * 8 + 4 * j + 1]),
                       sgn_i(w3[c * 8 + 4 * j + 2]), sgn_i(w3[c * 8 + 4 * j + 3]));
    }

    int lane = tid & 31;
    int cg   = tid >> 5;
    int b = blockIdx.y;
    int pos = blockIdx.x * 32 + lane;
    int cpos = min(pos, Lout - 1);

    int i = cpos + 2;
    float fi = __fadd_rn((float)i, 0.5f);
    float src = fmaxf(__fsub_rn(__fdiv_rn(fi, 5.0f), 0.5f), 0.0f);
    int i0 = (int)floorf(src);
    int i1 = min(i0 + 1, n - 1);
    float w = __fsub_rn(src, (float)i0);
    float w0 = __fsub_rn(1.0f, w);
    __syncthreads();

    const float* ip = in + (size_t)b * 64 * n;
#pragma unroll
    for (int g4 = 0; g4 < 2; g4++) {
        int word = 0;
#pragma unroll
        for (int by = 0; by < 4; by++) {
            int c = cg * 8 + g4 * 4 + by;
            float x0 = ip[(size_t)c * n + i0];   // already multiples of 1/64
            float x1 = ip[(size_t)c * n + i1];
            float val = __fadd_rn(__fmul_rn(x0, w0), __fmul_rn(x1, w));
            word |= (ltanh_i(val) & 255) << (8 * by);
        }
        stp[(cg * 2 + g4) * 32 + lane] = word;
    }
    __syncthreads();

    // conv1 64->8 (bin): warp cg computes output channel cg at each position
    {
        int acc = 0;
#pragma unroll
        for (int g = 0; g < 16; g++) acc = dp4a(stp[g * 32 + lane], w1p[cg * 16 + g], acc);
        s1b[lane * 8 + cg] = (uchar_t)tanh_of_int(acc);  // lbit identity on acc/64
    }
    __syncthreads();
    // conv2 8->8 (tanh'd weights)
    {
        const int* s1w = (const int*)s1b;
        int acc = dp4a(s1w[lane * 2], w2p[cg * 2], 0);
        acc = dp4a(s1w[lane * 2 + 1], w2p[cg * 2 + 1], acc);
        int idx = __float2int_rn(__fmul_rn((float)acc, 0.015625f));  // rint(acc/64)
        s2b[lane * 8 + cg] = (uchar_t)tanh_of_int(idx);
    }
    __syncthreads();

    const int* s2w = (const int*)s2b;
    int sw0 = s2w[lane * 2], sw1 = s2w[lane * 2 + 1];
    int v[8];
    int lmax = -1000000;
#pragma unroll
    for (int cc = 0; cc < 8; cc++) {
        int c = cg * 8 + cc;
        int acc = dp4a(sw0, w3p[c * 2], 0);
        acc = dp4a(sw1, w3p[c * 2 + 1], acc);
        v[cc] = acc;                  // value = acc/64, lbit identity
        lmax = max(lmax, acc);
    }
    red[cg * 32 + lane] = lmax;
    __syncthreads();
    int vmax = red[lane];
#pragma unroll
    for (int g = 1; g < 8; g++) vmax = max(vmax, red[g * 32 + lane]);
    __syncthreads();

    int lsum = 0;
#pragma unroll
    for (int cc = 0; cc < 8; cc++) {
        int o = g_smax_i[min(vmax - v[cc], 2048)];
        v[cc] = o;
        lsum += o;
    }
    red[cg * 32 + lane] = lsum;
    __syncthreads();
    int sum = red[lane];
#pragma unroll
    for (int g = 1; g < 8; g++) sum += red[g * 32 + lane];

    if (pos < Lout) {
        float sf = __fmul_rn((float)sum, 0.015625f);
        float* op = out + (size_t)b * 64 * Lout + pos;
#pragma unroll
        for (int cc = 0; cc < 8; cc++)
            op[(size_t)(cg * 8 + cc) * Lout] =
                lbitf(__fdiv_rn(__fmul_rn((float)v[cc], 0.015625f), sf));
    }
}

// ---------------------------------------------------------------------------
// K6: upsample(x4) + conv(64->8,bin) + conv(8->4) + crop + transpose. int path.
// ---------------------------------------------------------------------------
__global__ __launch_bounds__(128)
void k_up4(const float* __restrict__ in, const float* __restrict__ w4,
           const float* __restrict__ w5, float* __restrict__ out) {
    const int n = 1255;
    __shared__ int w4p[128];       // [o*16+g] signs packed
    __shared__ int w5p[8];         // [o*2+j] tanh'd ints packed
    __shared__ int hp[32 * 32];    // partial conv ints [(sub*8+o)][pos]

    int tid = threadIdx.x;
    for (int t = tid; t < 128; t += 128) {
        int o = t >> 4, g = t & 15;
        w4p[t] = pack4(sgn_i(w4[o * 64 + 4 * g + 0]), sgn_i(w4[o * 64 + 4 * g + 1]),
                       sgn_i(w4[o * 64 + 4 * g + 2]), sgn_i(w4[o * 64 + 4 * g + 3]));
    }
    if (tid < 8) {
        int o = tid >> 1, j = tid & 1;
        w5p[tid] = pack4(w_i(w5[o * 8 + 4 * j + 0]), w_i(w5[o * 8 + 4 * j + 1]),
                         w_i(w5[o * 8 + 4 * j + 2]), w_i(w5[o * 8 + 4 * j + 3]));
    }

    int lane = tid & 31;
    int sub  = tid >> 5;
    int b = blockIdx.y;
    int pos = blockIdx.x * 32 + lane;
    int cpos = min(pos, 4999);

    int i = cpos + 18;
    float fi = __fadd_rn((float)i, 0.5f);
    float src = fmaxf(__fsub_rn(__fdiv_rn(fi, 4.0f), 0.5f), 0.0f);
    int i0 = (int)floorf(src);
    int i1 = min(i0 + 1, n - 1);
    float w = __fsub_rn(src, (float)i0);
    float w0 = __fsub_rn(1.0f, w);
    __syncthreads();

    int h[8];
#pragma unroll
    for (int o = 0; o < 8; o++) h[o] = 0;
    const float* ip = in + (size_t)b * 64 * n;
#pragma unroll
    for (int g4 = 0; g4 < 4; g4++) {
        int word = 0;
#pragma unroll
        for (int by = 0; by < 4; by++) {
            int c = sub * 16 + g4 * 4 + by;
            float x0 = ip[(size_t)c * n + i0];
            float x1 = ip[(size_t)c * n + i1];
            float val = __fadd_rn(__fmul_rn(x0, w0), __fmul_rn(x1, w));
            word |= (ltanh_i(val) & 255) << (8 * by);
        }
#pragma unroll
        for (int o = 0; o < 8; o++) h[o] = dp4a(word, w4p[o * 16 + sub * 4 + g4], h[o]);
    }
#pragma unroll
    for (int o = 0; o < 8; o++) hp[(sub * 8 + o) * 32 + lane] = h[o];
    __syncthreads();

    if (sub == 0 && pos < 5000) {
        int t4[8];
#pragma unroll
        for (int o = 0; o < 8; o++) {
            int s = hp[o * 32 + lane] + hp[(8 + o) * 32 + lane] +
                    hp[(16 + o) * 32 + lane] + hp[(24 + o) * 32 + lane];
            t4[o] = tanh_of_int(s);   // lbit identity on s/64, tanh LUT on int
        }
        int wA = pack4(t4[0], t4[1], t4[2], t4[3]);
        int wB = pack4(t4[4], t4[5], t4[6], t4[7]);
        float rr[4];
#pragma unroll
        for (int o = 0; o < 4; o++) {
            int acc = dp4a(wA, w5p[o * 2], 0);
            acc = dp4a(wB, w5p[o * 2 + 1], acc);
            rr[o] = lbitf(__fmul_rn((float)acc, 2.44140625e-4f));  // acc/4096 exact
        }
        float4* o4 = (float4*)(out + ((size_t)b * 5000 + pos) * 4);
        *o4 = make_float4(rr[0], rr[1], rr[2], rr[3]);
    }
}

// ---------------------------------------------------------------------------
// Host launcher.
// ---------------------------------------------------------------------------
extern "C" void kernel_launch(void* const* d_in, const int* in_sizes, int n_in,
                              void* d_out, int out_size) {
    (void)in_sizes; (void)n_in; (void)out_size;
    float *b0, *b1;
    cudaGetSymbolAddress((void**)&b0, g_buf0);
    cudaGetSymbolAddress((void**)&b1, g_buf1);

    const float* W[15];
    for (int i = 0; i < 15; i++) W[i] = (const float*)d_in[i];
    float* out = (float*)d_out;

    k_init_luts<<<9, 256>>>();
    { int total = 128 * 1334; k_head<<<(total + 255) / 256, 256>>>(W[0], W[1], b0); }
    k_mid<5, 5, 8,  true ><<<dim3(34, 128), 256>>>(b0, 1334, 266, W[2], W[3], W[4], b1);
    k_mid<3, 1, 32, true ><<<dim3(9, 128),  256>>>(b1, 266, 260, W[5], W[6], W[7], b0);
    k_mid<5, 1, 32, false><<<dim3(8, 128),  256>>>(b0, 260, 252, W[8], W[9], nullptr, b1);
    k_up5<<<dim3(40, 128), 256>>>(b1, W[10], W[11], W[12], b0);
    k_up4<<<dim3(157, 128), 128>>>(b0, W[13], W[14], out);
}